// round 10
// baseline (speedup 1.0000x reference)
#include <cuda_runtime.h>

// ============================================================================
// PointNet++ part-seg forward, GB300 (sm_103a). Round 10:
//  - GEMM reverted to round-4 gemm4 (f32x2, 4 cols/thread, big grids) — the
//    round-7 blocked GEMM was occupancy-bound and 350us slower (measured)
//  - FPS keeps f32x2 packed distance update (measured -39us)
//  - launch order: split, skip0, fps1, knn1  -> knn1 lands in profiled slot 4
// ============================================================================

#define BB 8
#define NN 4096
#define KK 20

typedef unsigned long long ull;

// ---- float arena offsets --------------------------------------------------
#define OFF_XYZ   0
#define SZ_PTS    (BB*NN*3)
#define OFF_NRM   (OFF_XYZ + SZ_PTS)
#define OFF_X1    (OFF_NRM + SZ_PTS)
#define OFF_X2    (OFF_X1 + BB*512*3)
#define OFF_X3    (OFF_X2 + BB*256*3)
#define OFF_X4    (OFF_X3 + BB*128*3)
#define OFF_F1    (OFF_X4 + BB*64*3)
#define OFF_F2    (OFF_F1 + BB*512*64)
#define OFF_F3    (OFF_F2 + BB*256*128)
#define OFF_F4    (OFF_F3 + BB*128*256)
#define OFF_G3    (OFF_F4 + BB*64*512)
#define OFF_G2    (OFF_G3 + BB*128*512)
#define OFF_G1    (OFF_G2 + BB*256*256)
#define OFF_G0    (OFF_G1 + BB*512*128)
#define OFF_APROJ (OFF_G0 + BB*NN*128)          // max B*M*D = 8*4096*64
#define OFF_BPROJ (OFF_APROJ + 2097152)
#define OFF_IBUF  (OFF_BPROJ + 262144)          // max B*N*128
#define OFF_SK0   (OFF_IBUF + 4194304)
#define ARENA_SZ  (OFF_SK0 + BB*NN*22 + 512)

__device__ float g_arena[ARENA_SZ];
__device__ int   g_iarena[BB*512*KK];

// ---- packed f32x2 helpers --------------------------------------------------
__device__ __forceinline__ ull pack2s(float v) {
    ull r; unsigned u = __float_as_uint(v);
    asm("mov.b64 %0, {%1, %1};" : "=l"(r) : "r"(u));
    return r;
}
__device__ __forceinline__ ull pack2(float a, float b) {
    ull r; unsigned ua = __float_as_uint(a), ub = __float_as_uint(b);
    asm("mov.b64 %0, {%1, %2};" : "=l"(r) : "r"(ua), "r"(ub));
    return r;
}
__device__ __forceinline__ ull fma2(ull a, ull b, ull c) {
    ull d; asm("fma.rn.f32x2 %0, %1, %2, %3;" : "=l"(d) : "l"(a), "l"(b), "l"(c));
    return d;
}
__device__ __forceinline__ ull add2(ull a, ull b) {
    ull d; asm("add.rn.f32x2 %0, %1, %2;" : "=l"(d) : "l"(a), "l"(b));
    return d;
}
__device__ __forceinline__ ull mul2(ull a, ull b) {
    ull d; asm("mul.rn.f32x2 %0, %1, %2;" : "=l"(d) : "l"(a), "l"(b));
    return d;
}
__device__ __forceinline__ float2 unpack2(ull v) {
    unsigned lo, hi;
    asm("mov.b64 {%0, %1}, %2;" : "=r"(lo), "=r"(hi) : "l"(v));
    return make_float2(__uint_as_float(lo), __uint_as_float(hi));
}

// ---------------------------------------------------------------------------
// split x [B,6,N] -> xyz [B,N,3], nrm [B,N,3]
// ---------------------------------------------------------------------------
__global__ void split_kernel(const float* __restrict__ x,
                             float* __restrict__ xyz, float* __restrict__ nrm) {
    int i = blockIdx.x * blockDim.x + threadIdx.x;
    if (i >= BB * NN) return;
    int b = i / NN, n = i - b * NN;
    const float* base = x + (long)b * 6 * NN;
#pragma unroll
    for (int j = 0; j < 3; j++) {
        xyz[(long)i * 3 + j] = base[(long)j * NN + n];
        nrm[(long)i * 3 + j] = base[(long)(3 + j) * NN + n];
    }
}

// ---------------------------------------------------------------------------
// FPS, one block per batch, f32x2-packed distance update (lanes bit-identical
// to scalar add.rn/mul.rn/fma.rn). Matches JAX scan (first-index ties).
// ---------------------------------------------------------------------------
template<int THREADS, int PTS>
__global__ void fps_kernel(const float* __restrict__ src, long bStride,
                           int pStride, int cStride, int Npts, int S,
                           float* __restrict__ outXyz) {
    constexpr int NW = THREADS / 32;
    constexpr int PP = PTS / 2;
    extern __shared__ float sp[];
    float* sx = sp;
    float* sy = sp + Npts;
    float* sz = sp + 2 * Npts;
    __shared__ unsigned sv[2][NW > 1 ? NW : 1];
    __shared__ int      si[2][NW > 1 ? NW : 1];

    const int t = threadIdx.x;
    const int lane = t & 31;
    const int w = t >> 5;
    const float* base = src + (long)blockIdx.x * bStride;
    for (int i = t; i < Npts; i += THREADS) {
        sx[i] = base[(long)i * pStride];
        sy[i] = base[(long)i * pStride + cStride];
        sz[i] = base[(long)i * pStride + 2 * cStride];
    }
    __syncthreads();

    ull lxp[PP], lyp[PP], lzp[PP];
    float dist[PTS];
    const int tbase = t * PTS;
#pragma unroll
    for (int i = 0; i < PP; i++) {
        lxp[i] = pack2(sx[tbase + 2 * i], sx[tbase + 2 * i + 1]);
        lyp[i] = pack2(sy[tbase + 2 * i], sy[tbase + 2 * i + 1]);
        lzp[i] = pack2(sz[tbase + 2 * i], sz[tbase + 2 * i + 1]);
    }
#pragma unroll
    for (int i = 0; i < PTS; i++) dist[i] = 1e10f;

    float* outp = outXyz + (long)blockIdx.x * S * 3;
    int far = 0;
    for (int it = 0; it < S; ++it) {
        float fx = sx[far], fy = sy[far], fz = sz[far];
        if (t == 0) {
            outp[it * 3 + 0] = fx;
            outp[it * 3 + 1] = fy;
            outp[it * 3 + 2] = fz;
        }
        ull nfx = pack2s(-fx), nfy = pack2s(-fy), nfz = pack2s(-fz);
        float bestv = -1.0f;
        int besti = 0;
#pragma unroll
        for (int i = 0; i < PP; i++) {
            ull dx = add2(lxp[i], nfx);
            ull dy = add2(lyp[i], nfy);
            ull dz = add2(lzp[i], nfz);
            ull dd = mul2(dx, dx);
            dd = fma2(dy, dy, dd);
            dd = fma2(dz, dz, dd);
            float2 dp = unpack2(dd);
            float nd0 = fminf(dist[2 * i], dp.x);
            float nd1 = fminf(dist[2 * i + 1], dp.y);
            dist[2 * i] = nd0;
            dist[2 * i + 1] = nd1;
            if (nd0 > bestv) { bestv = nd0; besti = tbase + 2 * i; }
            if (nd1 > bestv) { bestv = nd1; besti = tbase + 2 * i + 1; }
        }
        unsigned bv = __float_as_uint(bestv);
        unsigned m = __reduce_max_sync(0xffffffffu, bv);
        unsigned bal = __ballot_sync(0xffffffffu, bv == m);
        int lead = __ffs((int)bal) - 1;
        int widx = __shfl_sync(0xffffffffu, besti, lead);
        if (THREADS == 32) {
            far = widx;
        } else {
            int p = it & 1;
            if (lane == 0) { sv[p][w] = m; si[p][w] = widx; }
            __syncthreads();
            unsigned v = (lane < NW) ? sv[p][lane] : 0u;
            int id = (lane < NW) ? si[p][lane] : 0;
            unsigned m2 = __reduce_max_sync(0xffffffffu, v);
            unsigned b2 = __ballot_sync(0xffffffffu, v == m2);
            int l2 = __ffs((int)b2) - 1;
            far = __shfl_sync(0xffffffffu, id, l2);
        }
    }
}

// ---------------------------------------------------------------------------
// kNN (K=20), expanded distance (matches ref). Register top-20, pending-
// candidate buffering of the warp-divergent insert.
// ---------------------------------------------------------------------------
__device__ __forceinline__ void knn_insert(float (&bd)[KK], int (&bi)[KK],
                                           float d, int mIdx) {
#pragma unroll
    for (int j = KK - 1; j >= 1; --j) {
        bool c1 = bd[j - 1] > d;
        bool c2 = bd[j] > d;
        float nbd = c1 ? bd[j - 1] : (c2 ? d : bd[j]);
        int   nbi = c1 ? bi[j - 1] : (c2 ? mIdx : bi[j]);
        bd[j] = nbd; bi[j] = nbi;
    }
    if (bd[0] > d) { bd[0] = d; bi[0] = mIdx; }
}

__global__ void knn_kernel(const float* __restrict__ q, int S,
                           const float* __restrict__ ref, int M,
                           int* __restrict__ out) {
    const int TILE = 512;
    __shared__ float4 sref[TILE];
    int nqb = (S + 127) / 128;
    int b  = blockIdx.x / nqb;
    int qi = (blockIdx.x % nqb) * 128 + threadIdx.x;
    bool valid = qi < S;
    float qx = 0, qy = 0, qz = 0, qq = 0;
    if (valid) {
        const float* qp = q + ((long)b * S + qi) * 3;
        qx = qp[0]; qy = qp[1]; qz = qp[2];
        qq = qx * qx + qy * qy + qz * qz;
    }
    float bd[KK]; int bi[KK];
#pragma unroll
    for (int j = 0; j < KK; j++) { bd[j] = 3.4e38f; bi[j] = 0; }
    float worst = 3.4e38f;
    float pd = 0.f; int pi = 0; bool pend = false;
    const float* rbase = ref + (long)b * M * 3;
    for (int m0 = 0; m0 < M; m0 += TILE) {
        int lim = min(TILE, M - m0);
        for (int j = threadIdx.x; j < lim; j += blockDim.x) {
            float rx = rbase[(m0 + j) * 3 + 0];
            float ry = rbase[(m0 + j) * 3 + 1];
            float rz = rbase[(m0 + j) * 3 + 2];
            sref[j] = make_float4(rx, ry, rz, rx * rx + ry * ry + rz * rz);
        }
        __syncthreads();
        for (int mm = 0; mm < lim; mm++) {
            float4 r = sref[mm];
            float dot = qx * r.x + qy * r.y + qz * r.z;
            float d = qq - 2.f * dot + r.w;
            bool acc = d < worst;
            bool must = acc && pend;
            if (__any_sync(0xffffffffu, must)) {
                if (pend) {
                    knn_insert(bd, bi, pd, pi);
                    pend = false;
                    worst = bd[KK - 1];
                }
            }
            if (acc) { pd = d; pi = m0 + mm; pend = true; }
        }
        __syncthreads();
    }
    if (pend) { knn_insert(bd, bi, pd, pi); }
    if (valid) {
        int* op = out + ((long)b * S + qi) * KK;
#pragma unroll
        for (int j = 0; j < KK; j++) op[j] = bi[j];
    }
}

// ---------------------------------------------------------------------------
// GEMM4 (round-4, measured-good): 4 output cols/thread via two fma.rn.f32x2;
// smem holds (v,v)-packed rows; adaptive row tile. Requires Cout % 4 == 0.
// ---------------------------------------------------------------------------
template<int RT>
__global__ void gemm4_kernel(const float* __restrict__ A1, int C1,
                             const float* __restrict__ A2, int C2,
                             const float* __restrict__ W,
                             const float* __restrict__ bias,
                             float* __restrict__ out,
                             int rows, int Cout, int relu) {
    extern __shared__ ull shu[];
    const int Cin = C1 + C2;
    int row0 = blockIdx.x * RT;
    for (int i = threadIdx.x; i < RT * Cin; i += blockDim.x) {
        int r = i / Cin, c = i - r * Cin;
        int row = row0 + r;
        float v = 0.f;
        if (row < rows) {
            if (c < C1) v = A1[(long)row * C1 + c];
            else        v = A2[(long)row * C2 + (c - C1)];
        }
        shu[i] = pack2s(v);
    }
    __syncthreads();
    int d0 = (blockIdx.y * blockDim.x + threadIdx.x) * 4;
    if (d0 >= Cout) return;
    ull acc0[RT], acc1[RT];
#pragma unroll
    for (int r = 0; r < RT; r++) { acc0[r] = 0ull; acc1[r] = 0ull; }
    for (int c = 0; c < Cin; c++) {
        ulonglong2 wv = *reinterpret_cast<const ulonglong2*>(W + (long)c * Cout + d0);
        const ull* shc = shu + c;
#pragma unroll
        for (int r = 0; r < RT; r++) {
            ull vv = shc[r * Cin];
            acc0[r] = fma2(vv, wv.x, acc0[r]);
            acc1[r] = fma2(vv, wv.y, acc1[r]);
        }
    }
    float4 bb = bias ? *reinterpret_cast<const float4*>(bias + d0)
                     : make_float4(0.f, 0.f, 0.f, 0.f);
#pragma unroll
    for (int r = 0; r < RT; r++) {
        int row = row0 + r;
        if (row < rows) {
            float2 p0 = unpack2(acc0[r]);
            float2 p1 = unpack2(acc1[r]);
            float v0 = p0.x + bb.x, v1 = p0.y + bb.y;
            float v2 = p1.x + bb.z, v3 = p1.y + bb.w;
            if (relu) {
                v0 = fmaxf(v0, 0.f); v1 = fmaxf(v1, 0.f);
                v2 = fmaxf(v2, 0.f); v3 = fmaxf(v3, 0.f);
            }
            *reinterpret_cast<float4*>(out + (long)row * Cout + d0) =
                make_float4(v0, v1, v2, v3);
        }
    }
}

// 2-col GEMM kept for Cout=50 (seg head)
__global__ void gemm2_kernel(const float* __restrict__ A1, int C1,
                             const float* __restrict__ W,
                             const float* __restrict__ bias,
                             float* __restrict__ out,
                             int rows, int Cout, int relu) {
    extern __shared__ float sh[];
    const int RT = 16;
    const int Cin = C1;
    int row0 = blockIdx.x * RT;
    for (int i = threadIdx.x; i < RT * Cin; i += blockDim.x) {
        int r = i / Cin, c = i - r * Cin;
        int row = row0 + r;
        sh[i] = (row < rows) ? A1[(long)row * C1 + c] : 0.f;
    }
    __syncthreads();
    int d0 = (blockIdx.y * blockDim.x + threadIdx.x) * 2;
    if (d0 >= Cout) return;
    float2 acc[RT];
#pragma unroll
    for (int r = 0; r < RT; r++) acc[r] = make_float2(0.f, 0.f);
    for (int c = 0; c < Cin; c++) {
        float2 w = *reinterpret_cast<const float2*>(W + (long)c * Cout + d0);
        const float* shc = sh + c;
#pragma unroll
        for (int r = 0; r < RT; r++) {
            float v = shc[r * Cin];
            acc[r].x = fmaf(v, w.x, acc[r].x);
            acc[r].y = fmaf(v, w.y, acc[r].y);
        }
    }
    float2 bb = bias ? *reinterpret_cast<const float2*>(bias + d0)
                     : make_float2(0.f, 0.f);
#pragma unroll
    for (int r = 0; r < RT; r++) {
        int row = row0 + r;
        if (row < rows) {
            float vx = acc[r].x + bb.x, vy = acc[r].y + bb.y;
            if (relu) { vx = fmaxf(vx, 0.f); vy = fmaxf(vy, 0.f); }
            *reinterpret_cast<float2*>(out + (long)row * Cout + d0) = make_float2(vx, vy);
        }
    }
}

// ---------------------------------------------------------------------------
// Fused gather-max: f[b,s,d] = relu( max_k A[b,nidx[b,s,k],d] - Bp[b,s,d] )
// ---------------------------------------------------------------------------
__global__ void gathermax_kernel(const float* __restrict__ A,
                                 const float* __restrict__ Bp,
                                 const int* __restrict__ nidx,
                                 float* __restrict__ f,
                                 int S, int M, int D) {
    __shared__ int idx[KK];
    int bs = blockIdx.x;
    int b = bs / S;
    if (threadIdx.x < KK) idx[threadIdx.x] = nidx[(long)bs * KK + threadIdx.x];
    __syncthreads();
    const float* Abase = A + (long)b * M * D;
    for (int d = threadIdx.x; d < D; d += blockDim.x) {
        float m = -3.4e38f;
#pragma unroll 4
        for (int k = 0; k < KK; k++)
            m = fmaxf(m, Abase[(long)idx[k] * D + d]);
        f[(long)bs * D + d] = fmaxf(m - Bp[(long)bs * D + d], 0.f);
    }
}

// ---------------------------------------------------------------------------
// 3-NN interp, two-phase (selection matches ref knn; weights ref fp_block).
// ---------------------------------------------------------------------------
__global__ void interp3_kernel(const float* __restrict__ xq, int Sq,
                               const float* __restrict__ xr, int Mr,
                               const float* __restrict__ fr, int C,
                               float* __restrict__ out) {
    __shared__ float rx[512], ry[512], rz[512], rr2[512];
    __shared__ float qw[128][3];
    __shared__ int   qb[128][3];
    int nqb = Sq / 128;
    int b  = blockIdx.x / nqb;
    int q0 = (blockIdx.x % nqb) * 128;
    const float* rp = xr + (long)b * Mr * 3;
    for (int j = threadIdx.x; j < Mr; j += blockDim.x) {
        float a = rp[j * 3 + 0], bb = rp[j * 3 + 1], cc = rp[j * 3 + 2];
        rx[j] = a; ry[j] = bb; rz[j] = cc;
        rr2[j] = a * a + bb * bb + cc * cc;
    }
    __syncthreads();
    {
        int qi = q0 + threadIdx.x;
        const float* qp = xq + ((long)b * Sq + qi) * 3;
        float qx = qp[0], qy = qp[1], qz = qp[2];
        float qq = qx * qx + qy * qy + qz * qz;
        float bd0 = 3.4e38f, bd1 = 3.4e38f, bd2 = 3.4e38f;
        int bi0 = 0, bi1 = 0, bi2 = 0;
        for (int m = 0; m < Mr; m++) {
            float d = qq - 2.f * (qx * rx[m] + qy * ry[m] + qz * rz[m]) + rr2[m];
            if (d < bd2) {
                if (d < bd1) {
                    if (d < bd0) { bd2 = bd1; bi2 = bi1; bd1 = bd0; bi1 = bi0; bd0 = d; bi0 = m; }
                    else         { bd2 = bd1; bi2 = bi1; bd1 = d; bi1 = m; }
                } else           { bd2 = d; bi2 = m; }
            }
        }
        int bis[3] = { bi0, bi1, bi2 };
        float w[3]; float ws = 0.f;
#pragma unroll
        for (int j = 0; j < 3; j++) {
            float dx = rx[bis[j]] - qx, dy = ry[bis[j]] - qy, dz = rz[bis[j]] - qz;
            float dd = dx * dx + dy * dy + dz * dz;
            w[j] = 1.f / (dd + 1e-8f);
            ws += w[j];
        }
#pragma unroll
        for (int j = 0; j < 3; j++) {
            qw[threadIdx.x][j] = w[j] / ws;
            qb[threadIdx.x][j] = bis[j];
        }
    }
    __syncthreads();
    for (int qv = 0; qv < 128; ++qv) {
        float w0 = qw[qv][0], w1 = qw[qv][1], w2 = qw[qv][2];
        const float* f0 = fr + ((long)b * Mr + qb[qv][0]) * C;
        const float* f1 = fr + ((long)b * Mr + qb[qv][1]) * C;
        const float* f2 = fr + ((long)b * Mr + qb[qv][2]) * C;
        long ro = ((long)b * Sq + q0 + qv) * C;
        for (int c = threadIdx.x; c < C; c += blockDim.x)
            out[ro + c] = w0 * f0[c] + w1 * f1[c] + w2 * f2[c];
    }
}

// FP0 skip: [cls(16) | xyz(3) | nrm(3)] width-22 rows
__global__ void fp0_skip_kernel(const float* __restrict__ cls,
                                const float* __restrict__ xyz,
                                const float* __restrict__ nrm,
                                float* __restrict__ sk) {
    int total = BB * NN * 22;
    int stride = gridDim.x * blockDim.x;
    for (int i = blockIdx.x * blockDim.x + threadIdx.x; i < total; i += stride) {
        int c = i % 22;
        int row = i / 22;
        int b = row / NN;
        float v;
        if (c < 16)      v = cls[b * 16 + c];
        else if (c < 19) v = xyz[(long)row * 3 + (c - 16)];
        else             v = nrm[(long)row * 3 + (c - 19)];
        sk[i] = v;
    }
}

__global__ void transpose_kernel(const float* __restrict__ in, float* __restrict__ out) {
    __shared__ float tile[32][33];
    int b = blockIdx.z;
    int n0 = blockIdx.x * 32, c0 = blockIdx.y * 32;
    int tx = threadIdx.x, ty = threadIdx.y;
    tile[ty][tx] = in[((long)b * NN + n0 + ty) * 128 + c0 + tx];
    __syncthreads();
    out[((long)b * 128 + c0 + ty) * NN + n0 + tx] = tile[tx][ty];
}

// ============================================================================
// host driver
// ============================================================================
static void launch_g4(const float* A1, int C1, const float* A2, int C2,
                      const float* W, const float* bias, float* out,
                      int rows, int Cout, int relu) {
    int bd = Cout / 4;
    if (bd < 32) bd = 32;
    if (bd > 128) bd = 128;
    int rt = (rows >= 8192) ? 16 : (rows >= 2048) ? 8 : (rows >= 1024) ? 4 : 2;
    dim3 g((rows + rt - 1) / rt, (Cout + bd * 4 - 1) / (bd * 4));
    size_t sm = (size_t)rt * (C1 + C2) * sizeof(ull);
    switch (rt) {
        case 16: gemm4_kernel<16><<<g, bd, sm>>>(A1, C1, A2, C2, W, bias, out, rows, Cout, relu); break;
        case 8:  gemm4_kernel<8><<<g, bd, sm>>>(A1, C1, A2, C2, W, bias, out, rows, Cout, relu); break;
        case 4:  gemm4_kernel<4><<<g, bd, sm>>>(A1, C1, A2, C2, W, bias, out, rows, Cout, relu); break;
        default: gemm4_kernel<2><<<g, bd, sm>>>(A1, C1, A2, C2, W, bias, out, rows, Cout, relu); break;
    }
}

extern "C" void kernel_launch(void* const* d_in, const int* in_sizes, int n_in,
                              void* d_out, int out_size) {
    const float* x    = (const float*)d_in[0];
    const float* cls  = (const float*)d_in[1];
    const float* W0 = (const float*)d_in[2];  const float* b0 = (const float*)d_in[3];
    const float* W1 = (const float*)d_in[4];  const float* b1 = (const float*)d_in[5];
    const float* W2 = (const float*)d_in[6];  const float* b2 = (const float*)d_in[7];
    const float* W3 = (const float*)d_in[8];  const float* b3 = (const float*)d_in[9];
    const float* F3 = (const float*)d_in[10]; const float* fb3 = (const float*)d_in[11];
    const float* F2 = (const float*)d_in[12]; const float* fb2 = (const float*)d_in[13];
    const float* F1 = (const float*)d_in[14]; const float* fb1 = (const float*)d_in[15];
    const float* F0 = (const float*)d_in[16]; const float* fb0 = (const float*)d_in[17];
    const float* Wseg = (const float*)d_in[18]; const float* bseg = (const float*)d_in[19];

    float* arena = 0; int* iar = 0;
    cudaGetSymbolAddress((void**)&arena, g_arena);
    cudaGetSymbolAddress((void**)&iar, g_iarena);

    float* xyz = arena + OFF_XYZ;
    float* nrm = arena + OFF_NRM;
    float* x1 = arena + OFF_X1; float* x2 = arena + OFF_X2;
    float* x3 = arena + OFF_X3; float* x4 = arena + OFF_X4;
    float* f1 = arena + OFF_F1; float* f2 = arena + OFF_F2;
    float* f3 = arena + OFF_F3; float* f4 = arena + OFF_F4;
    float* g3 = arena + OFF_G3; float* g2 = arena + OFF_G2;
    float* g1 = arena + OFF_G1; float* g0 = arena + OFF_G0;
    float* aproj = arena + OFF_APROJ;
    float* bproj = arena + OFF_BPROJ;
    float* ibuf  = arena + OFF_IBUF;
    float* sk0   = arena + OFF_SK0;
    int* knn = iar;

    cudaFuncSetAttribute((const void*)fps_kernel<512, 8>,
                         cudaFuncAttributeMaxDynamicSharedMemorySize, 3 * NN * 4);

    // launches 1-4: split, skip0, fps1, knn1  (knn1 -> profiled slot #4)
    split_kernel<<<(BB * NN + 255) / 256, 256>>>(x, xyz, nrm);                        // 1
    fp0_skip_kernel<<<(BB * NN * 22 + 255) / 256, 256>>>(cls, xyz, nrm, sk0);         // 2
    fps_kernel<512, 8><<<BB, 512, 3 * NN * 4>>>(x, (long)6 * NN, 1, NN, NN, 512, x1); // 3
    knn_kernel<<<BB * 4, 128>>>(x1, 512, xyz, NN, knn);                               // 4 <- profiled

    // ---- remaining FPS chain ----
    fps_kernel<128, 4><<<BB, 128, 3 * 512 * 4>>>(x1, 512 * 3, 3, 1, 512, 256, x2);
    fps_kernel<64, 4><<<BB, 64, 3 * 256 * 4>>>(x2, 256 * 3, 3, 1, 256, 128, x3);
    fps_kernel<32, 4><<<BB, 32, 3 * 128 * 4>>>(x3, 128 * 3, 3, 1, 128, 64, x4);

    // ---- SA1: 4096 -> 512 ----
    launch_g4(xyz, 3, nrm, 3, W0, b0, aproj, BB * NN, 64, 0);
    launch_g4(x1, 3, 0, 0, W0, 0, bproj, BB * 512, 64, 0);
    gathermax_kernel<<<BB * 512, 64>>>(aproj, bproj, knn, f1, 512, NN, 64);

    // ---- SA2: 512 -> 256 ----
    knn_kernel<<<BB * 2, 128>>>(x2, 256, x1, 512, knn);
    launch_g4(x1, 3, f1, 64, W1, b1, aproj, BB * 512, 128, 0);
    launch_g4(x2, 3, 0, 0, W1, 0, bproj, BB * 256, 128, 0);
    gathermax_kernel<<<BB * 256, 128>>>(aproj, bproj, knn, f2, 256, 512, 128);

    // ---- SA3: 256 -> 128 ----
    knn_kernel<<<BB, 128>>>(x3, 128, x2, 256, knn);
    launch_g4(x2, 3, f2, 128, W2, b2, aproj, BB * 256, 256, 0);
    launch_g4(x3, 3, 0, 0, W2, 0, bproj, BB * 128, 256, 0);
    gathermax_kernel<<<BB * 128, 128>>>(aproj, bproj, knn, f3, 128, 256, 256);

    // ---- SA4: 128 -> 64 ----
    knn_kernel<<<BB, 128>>>(x4, 64, x3, 128, knn);
    launch_g4(x3, 3, f3, 256, W3, b3, aproj, BB * 128, 512, 0);
    launch_g4(x4, 3, 0, 0, W3, 0, bproj, BB * 64, 512, 0);
    gathermax_kernel<<<BB * 64, 128>>>(aproj, bproj, knn, f4, 64, 128, 512);

    // ---- FP3 ----
    interp3_kernel<<<BB, 128>>>(x3, 128, x4, 64, f4, 512, ibuf);
    launch_g4(ibuf, 512, f3, 256, F3, fb3, g3, BB * 128, 512, 1);

    // ---- FP2 ----
    interp3_kernel<<<BB * 2, 128>>>(x2, 256, x3, 128, g3, 512, ibuf);
    launch_g4(ibuf, 512, f2, 128, F2, fb2, g2, BB * 256, 256, 1);

    // ---- FP1 ----
    interp3_kernel<<<BB * 4, 128>>>(x1, 512, x2, 256, g2, 256, ibuf);
    launch_g4(ibuf, 256, f1, 64, F1, fb1, g1, BB * 512, 128, 1);

    // ---- FP0 ----
    interp3_kernel<<<BB * 32, 128>>>(xyz, NN, x1, 512, g1, 128, ibuf);
    launch_g4(ibuf, 128, sk0, 22, F0, fb0, g0, BB * NN, 128, 1);

    // ---- seg head (Cout=50 -> 2-col kernel) ----
    {
        dim3 g((BB * NN + 15) / 16, 1);
        gemm2_kernel<<<g, 32, 16 * 128 * sizeof(float)>>>(
            g0, 128, Wseg, bseg, (float*)d_out, BB * NN, 50, 0);
    }

    // ---- g0 transposed ----
    const int RESULT_SZ = BB * NN * 50;
    const int G0T_SZ = BB * 128 * NN;
    if (out_size >= RESULT_SZ + G0T_SZ) {
        dim3 g(NN / 32, 128 / 32, BB);
        transpose_kernel<<<g, dim3(32, 32)>>>(g0, (float*)d_out + RESULT_SZ);
    }
}

// round 11
// speedup vs baseline: 1.2068x; 1.2068x over previous
#include <cuda_runtime.h>

// ============================================================================
// PointNet++ part-seg forward, GB300 (sm_103a). Round 11:
//  - kNN rewritten warp-per-query (32x parallelism), lane-local sorted top-20
//    + 20-round warp k-way merge. refs pre-packed (x,y,z,r2) float4.
//  - GEMM = round-4 gemm4 (measured-good). FPS = f32x2 (measured-good).
// ============================================================================

#define BB 8
#define NN 4096
#define KK 20

typedef unsigned long long ull;

// ---- float arena offsets --------------------------------------------------
#define OFF_XYZ   0
#define SZ_PTS    (BB*NN*3)
#define OFF_NRM   (OFF_XYZ + SZ_PTS)
#define OFF_X1    (OFF_NRM + SZ_PTS)
#define OFF_X2    (OFF_X1 + BB*512*3)
#define OFF_X3    (OFF_X2 + BB*256*3)
#define OFF_X4    (OFF_X3 + BB*128*3)
#define OFF_F1    (OFF_X4 + BB*64*3)
#define OFF_F2    (OFF_F1 + BB*512*64)
#define OFF_F3    (OFF_F2 + BB*256*128)
#define OFF_F4    (OFF_F3 + BB*128*256)
#define OFF_G3    (OFF_F4 + BB*64*512)
#define OFF_G2    (OFF_G3 + BB*128*512)
#define OFF_G1    (OFF_G2 + BB*256*256)
#define OFF_G0    (OFF_G1 + BB*512*128)
#define OFF_APROJ (OFF_G0 + BB*NN*128)          // max B*M*D = 8*4096*64
#define OFF_BPROJ (OFF_APROJ + 2097152)
#define OFF_IBUF  (OFF_BPROJ + 262144)          // max B*N*128
#define OFF_SK0   (OFF_IBUF + 4194304)
#define OFF_R4    (OFF_SK0 + BB*NN*22)          // float4 refs, max B*N entries
#define ARENA_SZ  (OFF_R4 + BB*NN*4 + 512)

__device__ float g_arena[ARENA_SZ];
__device__ int   g_iarena[BB*512*KK];

// ---- packed f32x2 helpers --------------------------------------------------
__device__ __forceinline__ ull pack2s(float v) {
    ull r; unsigned u = __float_as_uint(v);
    asm("mov.b64 %0, {%1, %1};" : "=l"(r) : "r"(u));
    return r;
}
__device__ __forceinline__ ull pack2(float a, float b) {
    ull r; unsigned ua = __float_as_uint(a), ub = __float_as_uint(b);
    asm("mov.b64 %0, {%1, %2};" : "=l"(r) : "r"(ua), "r"(ub));
    return r;
}
__device__ __forceinline__ ull fma2(ull a, ull b, ull c) {
    ull d; asm("fma.rn.f32x2 %0, %1, %2, %3;" : "=l"(d) : "l"(a), "l"(b), "l"(c));
    return d;
}
__device__ __forceinline__ ull add2(ull a, ull b) {
    ull d; asm("add.rn.f32x2 %0, %1, %2;" : "=l"(d) : "l"(a), "l"(b));
    return d;
}
__device__ __forceinline__ ull mul2(ull a, ull b) {
    ull d; asm("mul.rn.f32x2 %0, %1, %2;" : "=l"(d) : "l"(a), "l"(b));
    return d;
}
__device__ __forceinline__ float2 unpack2(ull v) {
    unsigned lo, hi;
    asm("mov.b64 {%0, %1}, %2;" : "=r"(lo), "=r"(hi) : "l"(v));
    return make_float2(__uint_as_float(lo), __uint_as_float(hi));
}

// ---------------------------------------------------------------------------
// split x [B,6,N] -> xyz [B,N,3], nrm [B,N,3]
// ---------------------------------------------------------------------------
__global__ void split_kernel(const float* __restrict__ x,
                             float* __restrict__ xyz, float* __restrict__ nrm) {
    int i = blockIdx.x * blockDim.x + threadIdx.x;
    if (i >= BB * NN) return;
    int b = i / NN, n = i - b * NN;
    const float* base = x + (long)b * 6 * NN;
#pragma unroll
    for (int j = 0; j < 3; j++) {
        xyz[(long)i * 3 + j] = base[(long)j * NN + n];
        nrm[(long)i * 3 + j] = base[(long)(3 + j) * NN + n];
    }
}

// pack [n,3] points into float4 (x,y,z,|p|^2)
__global__ void prep4_kernel(const float* __restrict__ pts, int n,
                             float4* __restrict__ out) {
    int i = blockIdx.x * blockDim.x + threadIdx.x;
    if (i >= n) return;
    float a = pts[3 * i], b = pts[3 * i + 1], c = pts[3 * i + 2];
    out[i] = make_float4(a, b, c, a * a + b * b + c * c);
}

// ---------------------------------------------------------------------------
// FPS, one block per batch, f32x2-packed distance update (lanes bit-identical
// to scalar rn ops). Matches JAX scan (first-index ties).
// ---------------------------------------------------------------------------
template<int THREADS, int PTS>
__global__ void fps_kernel(const float* __restrict__ src, long bStride,
                           int pStride, int cStride, int Npts, int S,
                           float* __restrict__ outXyz) {
    constexpr int NW = THREADS / 32;
    constexpr int PP = PTS / 2;
    extern __shared__ float sp[];
    float* sx = sp;
    float* sy = sp + Npts;
    float* sz = sp + 2 * Npts;
    __shared__ unsigned sv[2][NW > 1 ? NW : 1];
    __shared__ int      si[2][NW > 1 ? NW : 1];

    const int t = threadIdx.x;
    const int lane = t & 31;
    const int w = t >> 5;
    const float* base = src + (long)blockIdx.x * bStride;
    for (int i = t; i < Npts; i += THREADS) {
        sx[i] = base[(long)i * pStride];
        sy[i] = base[(long)i * pStride + cStride];
        sz[i] = base[(long)i * pStride + 2 * cStride];
    }
    __syncthreads();

    ull lxp[PP], lyp[PP], lzp[PP];
    float dist[PTS];
    const int tbase = t * PTS;
#pragma unroll
    for (int i = 0; i < PP; i++) {
        lxp[i] = pack2(sx[tbase + 2 * i], sx[tbase + 2 * i + 1]);
        lyp[i] = pack2(sy[tbase + 2 * i], sy[tbase + 2 * i + 1]);
        lzp[i] = pack2(sz[tbase + 2 * i], sz[tbase + 2 * i + 1]);
    }
#pragma unroll
    for (int i = 0; i < PTS; i++) dist[i] = 1e10f;

    float* outp = outXyz + (long)blockIdx.x * S * 3;
    int far = 0;
    for (int it = 0; it < S; ++it) {
        float fx = sx[far], fy = sy[far], fz = sz[far];
        if (t == 0) {
            outp[it * 3 + 0] = fx;
            outp[it * 3 + 1] = fy;
            outp[it * 3 + 2] = fz;
        }
        ull nfx = pack2s(-fx), nfy = pack2s(-fy), nfz = pack2s(-fz);
        float bestv = -1.0f;
        int besti = 0;
#pragma unroll
        for (int i = 0; i < PP; i++) {
            ull dx = add2(lxp[i], nfx);
            ull dy = add2(lyp[i], nfy);
            ull dz = add2(lzp[i], nfz);
            ull dd = mul2(dx, dx);
            dd = fma2(dy, dy, dd);
            dd = fma2(dz, dz, dd);
            float2 dp = unpack2(dd);
            float nd0 = fminf(dist[2 * i], dp.x);
            float nd1 = fminf(dist[2 * i + 1], dp.y);
            dist[2 * i] = nd0;
            dist[2 * i + 1] = nd1;
            if (nd0 > bestv) { bestv = nd0; besti = tbase + 2 * i; }
            if (nd1 > bestv) { bestv = nd1; besti = tbase + 2 * i + 1; }
        }
        unsigned bv = __float_as_uint(bestv);
        unsigned m = __reduce_max_sync(0xffffffffu, bv);
        unsigned bal = __ballot_sync(0xffffffffu, bv == m);
        int lead = __ffs((int)bal) - 1;
        int widx = __shfl_sync(0xffffffffu, besti, lead);
        if (THREADS == 32) {
            far = widx;
        } else {
            int p = it & 1;
            if (lane == 0) { sv[p][w] = m; si[p][w] = widx; }
            __syncthreads();
            unsigned v = (lane < NW) ? sv[p][lane] : 0u;
            int id = (lane < NW) ? si[p][lane] : 0;
            unsigned m2 = __reduce_max_sync(0xffffffffu, v);
            unsigned b2 = __ballot_sync(0xffffffffu, v == m2);
            int l2 = __ffs((int)b2) - 1;
            far = __shfl_sync(0xffffffffu, id, l2);
        }
    }
}

// ---------------------------------------------------------------------------
// sorted insertion (register-resident, fully unrolled, strict compares:
// equal distances keep the earlier/lower index ahead — matches stable top_k)
// ---------------------------------------------------------------------------
__device__ __forceinline__ void knn_insert(float (&bd)[KK], int (&bi)[KK],
                                           float d, int mIdx) {
#pragma unroll
    for (int j = KK - 1; j >= 1; --j) {
        bool c1 = bd[j - 1] > d;
        bool c2 = bd[j] > d;
        float nbd = c1 ? bd[j - 1] : (c2 ? d : bd[j]);
        int   nbi = c1 ? bi[j - 1] : (c2 ? mIdx : bi[j]);
        bd[j] = nbd; bi[j] = nbi;
    }
    if (bd[0] > d) { bd[0] = d; bi[0] = mIdx; }
}

// ---------------------------------------------------------------------------
// Warp-per-query kNN. Lane scans refs lane+32i (coalesced float4), keeps a
// lane-local sorted top-20, then 20-round warp merge: min head value (float
// shfl reduction — distances can be slightly negative), tie -> min index.
// Output is the exact top-20 SET (downstream use is order-invariant).
// Requires (B*S) % 8 == 0 and S % 8 == 0.
// ---------------------------------------------------------------------------
__global__ void __launch_bounds__(256)
knn_warp_kernel(const float* __restrict__ q, int S,
                const float4* __restrict__ refs4, int M,
                int* __restrict__ out) {
    int gw = (blockIdx.x * blockDim.x + threadIdx.x) >> 5;   // query id (b*S+s)
    int lane = threadIdx.x & 31;
    int b = gw / S;
    const float* qp = q + (long)gw * 3;
    float qx = qp[0], qy = qp[1], qz = qp[2];
    float qq = qx * qx + qy * qy + qz * qz;
    float bd[KK]; int bi[KK];
#pragma unroll
    for (int j = 0; j < KK; j++) { bd[j] = 3.4e38f; bi[j] = 0x7FFFFFFF; }
    const float4* rb = refs4 + (long)b * M;
    int nit = M >> 5;
#pragma unroll 1
    for (int i = 0; i < nit; i++) {
        int m = lane + (i << 5);
        float4 r = rb[m];
        float dot = qx * r.x + qy * r.y + qz * r.z;
        float d = qq - 2.f * dot + r.w;
        if (d < bd[KK - 1]) knn_insert(bd, bi, d, m);
    }
    // 20-round k-way merge across lanes
    int keep = 0;
#pragma unroll 1
    for (int j = 0; j < KK; j++) {
        float mv = bd[0];
#pragma unroll
        for (int o = 16; o; o >>= 1)
            mv = fminf(mv, __shfl_xor_sync(0xffffffffu, mv, o));
        unsigned cand = (bd[0] == mv) ? (unsigned)bi[0] : 0xFFFFFFFFu;
        unsigned widx = __reduce_min_sync(0xffffffffu, cand);
        if (lane == j) keep = (int)widx;
        if ((bd[0] == mv) && ((unsigned)bi[0] == widx)) {
#pragma unroll
            for (int t2 = 0; t2 < KK - 1; t2++) { bd[t2] = bd[t2 + 1]; bi[t2] = bi[t2 + 1]; }
            bd[KK - 1] = 3.4e38f; bi[KK - 1] = 0x7FFFFFFF;
        }
    }
    if (lane < KK) out[(long)gw * KK + lane] = keep;
}

// ---------------------------------------------------------------------------
// GEMM4 (measured-good): 4 output cols/thread via two fma.rn.f32x2;
// smem holds (v,v)-packed rows; adaptive row tile. Requires Cout % 4 == 0.
// ---------------------------------------------------------------------------
template<int RT>
__global__ void gemm4_kernel(const float* __restrict__ A1, int C1,
                             const float* __restrict__ A2, int C2,
                             const float* __restrict__ W,
                             const float* __restrict__ bias,
                             float* __restrict__ out,
                             int rows, int Cout, int relu) {
    extern __shared__ ull shu[];
    const int Cin = C1 + C2;
    int row0 = blockIdx.x * RT;
    for (int i = threadIdx.x; i < RT * Cin; i += blockDim.x) {
        int r = i / Cin, c = i - r * Cin;
        int row = row0 + r;
        float v = 0.f;
        if (row < rows) {
            if (c < C1) v = A1[(long)row * C1 + c];
            else        v = A2[(long)row * C2 + (c - C1)];
        }
        shu[i] = pack2s(v);
    }
    __syncthreads();
    int d0 = (blockIdx.y * blockDim.x + threadIdx.x) * 4;
    if (d0 >= Cout) return;
    ull acc0[RT], acc1[RT];
#pragma unroll
    for (int r = 0; r < RT; r++) { acc0[r] = 0ull; acc1[r] = 0ull; }
    for (int c = 0; c < Cin; c++) {
        ulonglong2 wv = *reinterpret_cast<const ulonglong2*>(W + (long)c * Cout + d0);
        const ull* shc = shu + c;
#pragma unroll
        for (int r = 0; r < RT; r++) {
            ull vv = shc[r * Cin];
            acc0[r] = fma2(vv, wv.x, acc0[r]);
            acc1[r] = fma2(vv, wv.y, acc1[r]);
        }
    }
    float4 bb = bias ? *reinterpret_cast<const float4*>(bias + d0)
                     : make_float4(0.f, 0.f, 0.f, 0.f);
#pragma unroll
    for (int r = 0; r < RT; r++) {
        int row = row0 + r;
        if (row < rows) {
            float2 p0 = unpack2(acc0[r]);
            float2 p1 = unpack2(acc1[r]);
            float v0 = p0.x + bb.x, v1 = p0.y + bb.y;
            float v2 = p1.x + bb.z, v3 = p1.y + bb.w;
            if (relu) {
                v0 = fmaxf(v0, 0.f); v1 = fmaxf(v1, 0.f);
                v2 = fmaxf(v2, 0.f); v3 = fmaxf(v3, 0.f);
            }
            *reinterpret_cast<float4*>(out + (long)row * Cout + d0) =
                make_float4(v0, v1, v2, v3);
        }
    }
}

// 2-col GEMM kept for Cout=50 (seg head)
__global__ void gemm2_kernel(const float* __restrict__ A1, int C1,
                             const float* __restrict__ W,
                             const float* __restrict__ bias,
                             float* __restrict__ out,
                             int rows, int Cout, int relu) {
    extern __shared__ float sh[];
    const int RT = 16;
    const int Cin = C1;
    int row0 = blockIdx.x * RT;
    for (int i = threadIdx.x; i < RT * Cin; i += blockDim.x) {
        int r = i / Cin, c = i - r * Cin;
        int row = row0 + r;
        sh[i] = (row < rows) ? A1[(long)row * C1 + c] : 0.f;
    }
    __syncthreads();
    int d0 = (blockIdx.y * blockDim.x + threadIdx.x) * 2;
    if (d0 >= Cout) return;
    float2 acc[RT];
#pragma unroll
    for (int r = 0; r < RT; r++) acc[r] = make_float2(0.f, 0.f);
    for (int c = 0; c < Cin; c++) {
        float2 w = *reinterpret_cast<const float2*>(W + (long)c * Cout + d0);
        const float* shc = sh + c;
#pragma unroll
        for (int r = 0; r < RT; r++) {
            float v = shc[r * Cin];
            acc[r].x = fmaf(v, w.x, acc[r].x);
            acc[r].y = fmaf(v, w.y, acc[r].y);
        }
    }
    float2 bb = bias ? *reinterpret_cast<const float2*>(bias + d0)
                     : make_float2(0.f, 0.f);
#pragma unroll
    for (int r = 0; r < RT; r++) {
        int row = row0 + r;
        if (row < rows) {
            float vx = acc[r].x + bb.x, vy = acc[r].y + bb.y;
            if (relu) { vx = fmaxf(vx, 0.f); vy = fmaxf(vy, 0.f); }
            *reinterpret_cast<float2*>(out + (long)row * Cout + d0) = make_float2(vx, vy);
        }
    }
}

// ---------------------------------------------------------------------------
// Fused gather-max: f[b,s,d] = relu( max_k A[b,nidx[b,s,k],d] - Bp[b,s,d] )
// ---------------------------------------------------------------------------
__global__ void gathermax_kernel(const float* __restrict__ A,
                                 const float* __restrict__ Bp,
                                 const int* __restrict__ nidx,
                                 float* __restrict__ f,
                                 int S, int M, int D) {
    __shared__ int idx[KK];
    int bs = blockIdx.x;
    int b = bs / S;
    if (threadIdx.x < KK) idx[threadIdx.x] = nidx[(long)bs * KK + threadIdx.x];
    __syncthreads();
    const float* Abase = A + (long)b * M * D;
    for (int d = threadIdx.x; d < D; d += blockDim.x) {
        float m = -3.4e38f;
#pragma unroll 4
        for (int k = 0; k < KK; k++)
            m = fmaxf(m, Abase[(long)idx[k] * D + d]);
        f[(long)bs * D + d] = fmaxf(m - Bp[(long)bs * D + d], 0.f);
    }
}

// ---------------------------------------------------------------------------
// 3-NN interp, two-phase (selection matches ref knn; weights ref fp_block).
// ---------------------------------------------------------------------------
__global__ void interp3_kernel(const float* __restrict__ xq, int Sq,
                               const float* __restrict__ xr, int Mr,
                               const float* __restrict__ fr, int C,
                               float* __restrict__ out) {
    __shared__ float rx[512], ry[512], rz[512], rr2[512];
    __shared__ float qw[128][3];
    __shared__ int   qb[128][3];
    int nqb = Sq / 128;
    int b  = blockIdx.x / nqb;
    int q0 = (blockIdx.x % nqb) * 128;
    const float* rp = xr + (long)b * Mr * 3;
    for (int j = threadIdx.x; j < Mr; j += blockDim.x) {
        float a = rp[j * 3 + 0], bb = rp[j * 3 + 1], cc = rp[j * 3 + 2];
        rx[j] = a; ry[j] = bb; rz[j] = cc;
        rr2[j] = a * a + bb * bb + cc * cc;
    }
    __syncthreads();
    {
        int qi = q0 + threadIdx.x;
        const float* qp = xq + ((long)b * Sq + qi) * 3;
        float qx = qp[0], qy = qp[1], qz = qp[2];
        float qq = qx * qx + qy * qy + qz * qz;
        float bd0 = 3.4e38f, bd1 = 3.4e38f, bd2 = 3.4e38f;
        int bi0 = 0, bi1 = 0, bi2 = 0;
        for (int m = 0; m < Mr; m++) {
            float d = qq - 2.f * (qx * rx[m] + qy * ry[m] + qz * rz[m]) + rr2[m];
            if (d < bd2) {
                if (d < bd1) {
                    if (d < bd0) { bd2 = bd1; bi2 = bi1; bd1 = bd0; bi1 = bi0; bd0 = d; bi0 = m; }
                    else         { bd2 = bd1; bi2 = bi1; bd1 = d; bi1 = m; }
                } else           { bd2 = d; bi2 = m; }
            }
        }
        int bis[3] = { bi0, bi1, bi2 };
        float w[3]; float ws = 0.f;
#pragma unroll
        for (int j = 0; j < 3; j++) {
            float dx = rx[bis[j]] - qx, dy = ry[bis[j]] - qy, dz = rz[bis[j]] - qz;
            float dd = dx * dx + dy * dy + dz * dz;
            w[j] = 1.f / (dd + 1e-8f);
            ws += w[j];
        }
#pragma unroll
        for (int j = 0; j < 3; j++) {
            qw[threadIdx.x][j] = w[j] / ws;
            qb[threadIdx.x][j] = bis[j];
        }
    }
    __syncthreads();
    for (int qv = 0; qv < 128; ++qv) {
        float w0 = qw[qv][0], w1 = qw[qv][1], w2 = qw[qv][2];
        const float* f0 = fr + ((long)b * Mr + qb[qv][0]) * C;
        const float* f1 = fr + ((long)b * Mr + qb[qv][1]) * C;
        const float* f2 = fr + ((long)b * Mr + qb[qv][2]) * C;
        long ro = ((long)b * Sq + q0 + qv) * C;
        for (int c = threadIdx.x; c < C; c += blockDim.x)
            out[ro + c] = w0 * f0[c] + w1 * f1[c] + w2 * f2[c];
    }
}

// FP0 skip: [cls(16) | xyz(3) | nrm(3)] width-22 rows
__global__ void fp0_skip_kernel(const float* __restrict__ cls,
                                const float* __restrict__ xyz,
                                const float* __restrict__ nrm,
                                float* __restrict__ sk) {
    int total = BB * NN * 22;
    int stride = gridDim.x * blockDim.x;
    for (int i = blockIdx.x * blockDim.x + threadIdx.x; i < total; i += stride) {
        int c = i % 22;
        int row = i / 22;
        int b = row / NN;
        float v;
        if (c < 16)      v = cls[b * 16 + c];
        else if (c < 19) v = xyz[(long)row * 3 + (c - 16)];
        else             v = nrm[(long)row * 3 + (c - 19)];
        sk[i] = v;
    }
}

__global__ void transpose_kernel(const float* __restrict__ in, float* __restrict__ out) {
    __shared__ float tile[32][33];
    int b = blockIdx.z;
    int n0 = blockIdx.x * 32, c0 = blockIdx.y * 32;
    int tx = threadIdx.x, ty = threadIdx.y;
    tile[ty][tx] = in[((long)b * NN + n0 + ty) * 128 + c0 + tx];
    __syncthreads();
    out[((long)b * 128 + c0 + ty) * NN + n0 + tx] = tile[tx][ty];
}

// ============================================================================
// host driver
// ============================================================================
static void launch_g4(const float* A1, int C1, const float* A2, int C2,
                      const float* W, const float* bias, float* out,
                      int rows, int Cout, int relu) {
    int bd = Cout / 4;
    if (bd < 32) bd = 32;
    if (bd > 128) bd = 128;
    int rt = (rows >= 8192) ? 16 : (rows >= 2048) ? 8 : (rows >= 1024) ? 4 : 2;
    dim3 g((rows + rt - 1) / rt, (Cout + bd * 4 - 1) / (bd * 4));
    size_t sm = (size_t)rt * (C1 + C2) * sizeof(ull);
    switch (rt) {
        case 16: gemm4_kernel<16><<<g, bd, sm>>>(A1, C1, A2, C2, W, bias, out, rows, Cout, relu); break;
        case 8:  gemm4_kernel<8><<<g, bd, sm>>>(A1, C1, A2, C2, W, bias, out, rows, Cout, relu); break;
        case 4:  gemm4_kernel<4><<<g, bd, sm>>>(A1, C1, A2, C2, W, bias, out, rows, Cout, relu); break;
        default: gemm4_kernel<2><<<g, bd, sm>>>(A1, C1, A2, C2, W, bias, out, rows, Cout, relu); break;
    }
}

extern "C" void kernel_launch(void* const* d_in, const int* in_sizes, int n_in,
                              void* d_out, int out_size) {
    const float* x    = (const float*)d_in[0];
    const float* cls  = (const float*)d_in[1];
    const float* W0 = (const float*)d_in[2];  const float* b0 = (const float*)d_in[3];
    const float* W1 = (const float*)d_in[4];  const float* b1 = (const float*)d_in[5];
    const float* W2 = (const float*)d_in[6];  const float* b2 = (const float*)d_in[7];
    const float* W3 = (const float*)d_in[8];  const float* b3 = (const float*)d_in[9];
    const float* F3 = (const float*)d_in[10]; const float* fb3 = (const float*)d_in[11];
    const float* F2 = (const float*)d_in[12]; const float* fb2 = (const float*)d_in[13];
    const float* F1 = (const float*)d_in[14]; const float* fb1 = (const float*)d_in[15];
    const float* F0 = (const float*)d_in[16]; const float* fb0 = (const float*)d_in[17];
    const float* Wseg = (const float*)d_in[18]; const float* bseg = (const float*)d_in[19];

    float* arena = 0; int* iar = 0;
    cudaGetSymbolAddress((void**)&arena, g_arena);
    cudaGetSymbolAddress((void**)&iar, g_iarena);

    float* xyz = arena + OFF_XYZ;
    float* nrm = arena + OFF_NRM;
    float* x1 = arena + OFF_X1; float* x2 = arena + OFF_X2;
    float* x3 = arena + OFF_X3; float* x4 = arena + OFF_X4;
    float* f1 = arena + OFF_F1; float* f2 = arena + OFF_F2;
    float* f3 = arena + OFF_F3; float* f4 = arena + OFF_F4;
    float* g3 = arena + OFF_G3; float* g2 = arena + OFF_G2;
    float* g1 = arena + OFF_G1; float* g0 = arena + OFF_G0;
    float* aproj = arena + OFF_APROJ;
    float* bproj = arena + OFF_BPROJ;
    float* ibuf  = arena + OFF_IBUF;
    float* sk0   = arena + OFF_SK0;
    float4* r4   = (float4*)(arena + OFF_R4);
    int* knn = iar;

    cudaFuncSetAttribute((const void*)fps_kernel<512, 8>,
                         cudaFuncAttributeMaxDynamicSharedMemorySize, 3 * NN * 4);

    // launches 1-4: split, prep4(xyz), fps1, knn1  (knn1 -> profiled slot #4)
    split_kernel<<<(BB * NN + 255) / 256, 256>>>(x, xyz, nrm);                        // 1
    prep4_kernel<<<(BB * NN + 255) / 256, 256>>>(xyz, BB * NN, r4);                   // 2
    fps_kernel<512, 8><<<BB, 512, 3 * NN * 4>>>(x, (long)6 * NN, 1, NN, NN, 512, x1); // 3
    knn_warp_kernel<<<BB * 512 / 8, 256>>>(x1, 512, r4, NN, knn);                     // 4 <- profiled

    fp0_skip_kernel<<<(BB * NN * 22 + 255) / 256, 256>>>(cls, xyz, nrm, sk0);

    // ---- remaining FPS chain ----
    fps_kernel<128, 4><<<BB, 128, 3 * 512 * 4>>>(x1, 512 * 3, 3, 1, 512, 256, x2);
    fps_kernel<64, 4><<<BB, 64, 3 * 256 * 4>>>(x2, 256 * 3, 3, 1, 256, 128, x3);
    fps_kernel<32, 4><<<BB, 32, 3 * 128 * 4>>>(x3, 128 * 3, 3, 1, 128, 64, x4);

    // ---- SA1: 4096 -> 512 ----
    launch_g4(xyz, 3, nrm, 3, W0, b0, aproj, BB * NN, 64, 0);
    launch_g4(x1, 3, 0, 0, W0, 0, bproj, BB * 512, 64, 0);
    gathermax_kernel<<<BB * 512, 64>>>(aproj, bproj, knn, f1, 512, NN, 64);

    // ---- SA2: 512 -> 256 ----
    prep4_kernel<<<(BB * 512 + 255) / 256, 256>>>(x1, BB * 512, r4);
    knn_warp_kernel<<<BB * 256 / 8, 256>>>(x2, 256, r4, 512, knn);
    launch_g4(x1, 3, f1, 64, W1, b1, aproj, BB * 512, 128, 0);
    launch_g4(x2, 3, 0, 0, W1, 0, bproj, BB * 256, 128, 0);
    gathermax_kernel<<<BB * 256, 128>>>(aproj, bproj, knn, f2, 256, 512, 128);

    // ---- SA3: 256 -> 128 ----
    prep4_kernel<<<(BB * 256 + 255) / 256, 256>>>(x2, BB * 256, r4);
    knn_warp_kernel<<<BB * 128 / 8, 256>>>(x3, 128, r4, 256, knn);
    launch_g4(x2, 3, f2, 128, W2, b2, aproj, BB * 256, 256, 0);
    launch_g4(x3, 3, 0, 0, W2, 0, bproj, BB * 128, 256, 0);
    gathermax_kernel<<<BB * 128, 128>>>(aproj, bproj, knn, f3, 128, 256, 256);

    // ---- SA4: 128 -> 64 ----
    prep4_kernel<<<(BB * 128 + 255) / 256, 256>>>(x3, BB * 128, r4);
    knn_warp_kernel<<<BB * 64 / 8, 256>>>(x4, 64, r4, 128, knn);
    launch_g4(x3, 3, f3, 256, W3, b3, aproj, BB * 128, 512, 0);
    launch_g4(x4, 3, 0, 0, W3, 0, bproj, BB * 64, 512, 0);
    gathermax_kernel<<<BB * 64, 128>>>(aproj, bproj, knn, f4, 64, 128, 512);

    // ---- FP3 ----
    interp3_kernel<<<BB, 128>>>(x3, 128, x4, 64, f4, 512, ibuf);
    launch_g4(ibuf, 512, f3, 256, F3, fb3, g3, BB * 128, 512, 1);

    // ---- FP2 ----
    interp3_kernel<<<BB * 2, 128>>>(x2, 256, x3, 128, g3, 512, ibuf);
    launch_g4(ibuf, 512, f2, 128, F2, fb2, g2, BB * 256, 256, 1);

    // ---- FP1 ----
    interp3_kernel<<<BB * 4, 128>>>(x1, 512, x2, 256, g2, 256, ibuf);
    launch_g4(ibuf, 256, f1, 64, F1, fb1, g1, BB * 512, 128, 1);

    // ---- FP0 ----
    interp3_kernel<<<BB * 32, 128>>>(xyz, NN, x1, 512, g1, 128, ibuf);
    launch_g4(ibuf, 128, sk0, 22, F0, fb0, g0, BB * NN, 128, 1);

    // ---- seg head (Cout=50 -> 2-col kernel) ----
    {
        dim3 g((BB * NN + 15) / 16, 1);
        gemm2_kernel<<<g, 32, 16 * 128 * sizeof(float)>>>(
            g0, 128, Wseg, bseg, (float*)d_out, BB * NN, 50, 0);
    }

    // ---- g0 transposed ----
    const int RESULT_SZ = BB * NN * 50;
    const int G0T_SZ = BB * 128 * NN;
    if (out_size >= RESULT_SZ + G0T_SZ) {
        dim3 g(NN / 32, 128 / 32, BB);
        transpose_kernel<<<g, dim3(32, 32)>>>(g0, (float*)d_out + RESULT_SZ);
    }
}

// round 12
// speedup vs baseline: 1.8318x; 1.5179x over previous
#include <cuda_runtime.h>

// ============================================================================
// PointNet++ part-seg forward, GB300 (sm_103a). Round 12:
//  - Multi-stream overlap: FPS chain (8 SMs) on a side stream, forked/joined
//    with events; knn/GEMM/gathermax run concurrently on the main stream.
//  - Kernels identical to Round-11 measured set (knn_warp 209us, f32x2 FPS,
//    gemm4).
// ============================================================================

#define BB 8
#define NN 4096
#define KK 20

typedef unsigned long long ull;

// ---- float arena offsets --------------------------------------------------
#define OFF_XYZ   0
#define SZ_PTS    (BB*NN*3)
#define OFF_NRM   (OFF_XYZ + SZ_PTS)
#define OFF_X1    (OFF_NRM + SZ_PTS)
#define OFF_X2    (OFF_X1 + BB*512*3)
#define OFF_X3    (OFF_X2 + BB*256*3)
#define OFF_X4    (OFF_X3 + BB*128*3)
#define OFF_F1    (OFF_X4 + BB*64*3)
#define OFF_F2    (OFF_F1 + BB*512*64)
#define OFF_F3    (OFF_F2 + BB*256*128)
#define OFF_F4    (OFF_F3 + BB*128*256)
#define OFF_G3    (OFF_F4 + BB*64*512)
#define OFF_G2    (OFF_G3 + BB*128*512)
#define OFF_G1    (OFF_G2 + BB*256*256)
#define OFF_G0    (OFF_G1 + BB*512*128)
#define OFF_APROJ (OFF_G0 + BB*NN*128)          // max B*M*D = 8*4096*64
#define OFF_BPROJ (OFF_APROJ + 2097152)
#define OFF_IBUF  (OFF_BPROJ + 262144)          // max B*N*128
#define OFF_SK0   (OFF_IBUF + 4194304)
#define OFF_R4    (OFF_SK0 + BB*NN*22)          // float4 refs, max B*N entries
#define ARENA_SZ  (OFF_R4 + BB*NN*4 + 512)

__device__ float g_arena[ARENA_SZ];
__device__ int   g_iarena[BB*512*KK];

// ---- packed f32x2 helpers --------------------------------------------------
__device__ __forceinline__ ull pack2s(float v) {
    ull r; unsigned u = __float_as_uint(v);
    asm("mov.b64 %0, {%1, %1};" : "=l"(r) : "r"(u));
    return r;
}
__device__ __forceinline__ ull pack2(float a, float b) {
    ull r; unsigned ua = __float_as_uint(a), ub = __float_as_uint(b);
    asm("mov.b64 %0, {%1, %2};" : "=l"(r) : "r"(ua), "r"(ub));
    return r;
}
__device__ __forceinline__ ull fma2(ull a, ull b, ull c) {
    ull d; asm("fma.rn.f32x2 %0, %1, %2, %3;" : "=l"(d) : "l"(a), "l"(b), "l"(c));
    return d;
}
__device__ __forceinline__ ull add2(ull a, ull b) {
    ull d; asm("add.rn.f32x2 %0, %1, %2;" : "=l"(d) : "l"(a), "l"(b));
    return d;
}
__device__ __forceinline__ ull mul2(ull a, ull b) {
    ull d; asm("mul.rn.f32x2 %0, %1, %2;" : "=l"(d) : "l"(a), "l"(b));
    return d;
}
__device__ __forceinline__ float2 unpack2(ull v) {
    unsigned lo, hi;
    asm("mov.b64 {%0, %1}, %2;" : "=r"(lo), "=r"(hi) : "l"(v));
    return make_float2(__uint_as_float(lo), __uint_as_float(hi));
}

// ---------------------------------------------------------------------------
// split x [B,6,N] -> xyz [B,N,3], nrm [B,N,3]
// ---------------------------------------------------------------------------
__global__ void split_kernel(const float* __restrict__ x,
                             float* __restrict__ xyz, float* __restrict__ nrm) {
    int i = blockIdx.x * blockDim.x + threadIdx.x;
    if (i >= BB * NN) return;
    int b = i / NN, n = i - b * NN;
    const float* base = x + (long)b * 6 * NN;
#pragma unroll
    for (int j = 0; j < 3; j++) {
        xyz[(long)i * 3 + j] = base[(long)j * NN + n];
        nrm[(long)i * 3 + j] = base[(long)(3 + j) * NN + n];
    }
}

// pack [n,3] points into float4 (x,y,z,|p|^2)
__global__ void prep4_kernel(const float* __restrict__ pts, int n,
                             float4* __restrict__ out) {
    int i = blockIdx.x * blockDim.x + threadIdx.x;
    if (i >= n) return;
    float a = pts[3 * i], b = pts[3 * i + 1], c = pts[3 * i + 2];
    out[i] = make_float4(a, b, c, a * a + b * b + c * c);
}

// ---------------------------------------------------------------------------
// FPS, one block per batch, f32x2-packed distance update (lanes bit-identical
// to scalar rn ops). Matches JAX scan (first-index ties).
// ---------------------------------------------------------------------------
template<int THREADS, int PTS>
__global__ void fps_kernel(const float* __restrict__ src, long bStride,
                           int pStride, int cStride, int Npts, int S,
                           float* __restrict__ outXyz) {
    constexpr int NW = THREADS / 32;
    constexpr int PP = PTS / 2;
    extern __shared__ float sp[];
    float* sx = sp;
    float* sy = sp + Npts;
    float* sz = sp + 2 * Npts;
    __shared__ unsigned sv[2][NW > 1 ? NW : 1];
    __shared__ int      si[2][NW > 1 ? NW : 1];

    const int t = threadIdx.x;
    const int lane = t & 31;
    const int w = t >> 5;
    const float* base = src + (long)blockIdx.x * bStride;
    for (int i = t; i < Npts; i += THREADS) {
        sx[i] = base[(long)i * pStride];
        sy[i] = base[(long)i * pStride + cStride];
        sz[i] = base[(long)i * pStride + 2 * cStride];
    }
    __syncthreads();

    ull lxp[PP], lyp[PP], lzp[PP];
    float dist[PTS];
    const int tbase = t * PTS;
#pragma unroll
    for (int i = 0; i < PP; i++) {
        lxp[i] = pack2(sx[tbase + 2 * i], sx[tbase + 2 * i + 1]);
        lyp[i] = pack2(sy[tbase + 2 * i], sy[tbase + 2 * i + 1]);
        lzp[i] = pack2(sz[tbase + 2 * i], sz[tbase + 2 * i + 1]);
    }
#pragma unroll
    for (int i = 0; i < PTS; i++) dist[i] = 1e10f;

    float* outp = outXyz + (long)blockIdx.x * S * 3;
    int far = 0;
    for (int it = 0; it < S; ++it) {
        float fx = sx[far], fy = sy[far], fz = sz[far];
        if (t == 0) {
            outp[it * 3 + 0] = fx;
            outp[it * 3 + 1] = fy;
            outp[it * 3 + 2] = fz;
        }
        ull nfx = pack2s(-fx), nfy = pack2s(-fy), nfz = pack2s(-fz);
        float bestv = -1.0f;
        int besti = 0;
#pragma unroll
        for (int i = 0; i < PP; i++) {
            ull dx = add2(lxp[i], nfx);
            ull dy = add2(lyp[i], nfy);
            ull dz = add2(lzp[i], nfz);
            ull dd = mul2(dx, dx);
            dd = fma2(dy, dy, dd);
            dd = fma2(dz, dz, dd);
            float2 dp = unpack2(dd);
            float nd0 = fminf(dist[2 * i], dp.x);
            float nd1 = fminf(dist[2 * i + 1], dp.y);
            dist[2 * i] = nd0;
            dist[2 * i + 1] = nd1;
            if (nd0 > bestv) { bestv = nd0; besti = tbase + 2 * i; }
            if (nd1 > bestv) { bestv = nd1; besti = tbase + 2 * i + 1; }
        }
        unsigned bv = __float_as_uint(bestv);
        unsigned m = __reduce_max_sync(0xffffffffu, bv);
        unsigned bal = __ballot_sync(0xffffffffu, bv == m);
        int lead = __ffs((int)bal) - 1;
        int widx = __shfl_sync(0xffffffffu, besti, lead);
        if (THREADS == 32) {
            far = widx;
        } else {
            int p = it & 1;
            if (lane == 0) { sv[p][w] = m; si[p][w] = widx; }
            __syncthreads();
            unsigned v = (lane < NW) ? sv[p][lane] : 0u;
            int id = (lane < NW) ? si[p][lane] : 0;
            unsigned m2 = __reduce_max_sync(0xffffffffu, v);
            unsigned b2 = __ballot_sync(0xffffffffu, v == m2);
            int l2 = __ffs((int)b2) - 1;
            far = __shfl_sync(0xffffffffu, id, l2);
        }
    }
}

// ---------------------------------------------------------------------------
// sorted insertion (register-resident, fully unrolled, strict compares)
// ---------------------------------------------------------------------------
__device__ __forceinline__ void knn_insert(float (&bd)[KK], int (&bi)[KK],
                                           float d, int mIdx) {
#pragma unroll
    for (int j = KK - 1; j >= 1; --j) {
        bool c1 = bd[j - 1] > d;
        bool c2 = bd[j] > d;
        float nbd = c1 ? bd[j - 1] : (c2 ? d : bd[j]);
        int   nbi = c1 ? bi[j - 1] : (c2 ? mIdx : bi[j]);
        bd[j] = nbd; bi[j] = nbi;
    }
    if (bd[0] > d) { bd[0] = d; bi[0] = mIdx; }
}

// ---------------------------------------------------------------------------
// Warp-per-query kNN (measured 209us on knn1). Lane-local sorted top-20 +
// 20-round warp merge (min value, tie -> min index). Exact top-20 set.
// ---------------------------------------------------------------------------
__global__ void __launch_bounds__(256)
knn_warp_kernel(const float* __restrict__ q, int S,
                const float4* __restrict__ refs4, int M,
                int* __restrict__ out) {
    int gw = (blockIdx.x * blockDim.x + threadIdx.x) >> 5;   // query id (b*S+s)
    int lane = threadIdx.x & 31;
    int b = gw / S;
    const float* qp = q + (long)gw * 3;
    float qx = qp[0], qy = qp[1], qz = qp[2];
    float qq = qx * qx + qy * qy + qz * qz;
    float bd[KK]; int bi[KK];
#pragma unroll
    for (int j = 0; j < KK; j++) { bd[j] = 3.4e38f; bi[j] = 0x7FFFFFFF; }
    const float4* rb = refs4 + (long)b * M;
    int nit = M >> 5;
#pragma unroll 1
    for (int i = 0; i < nit; i++) {
        int m = lane + (i << 5);
        float4 r = rb[m];
        float dot = qx * r.x + qy * r.y + qz * r.z;
        float d = qq - 2.f * dot + r.w;
        if (d < bd[KK - 1]) knn_insert(bd, bi, d, m);
    }
    int keep = 0;
#pragma unroll 1
    for (int j = 0; j < KK; j++) {
        float mv = bd[0];
#pragma unroll
        for (int o = 16; o; o >>= 1)
            mv = fminf(mv, __shfl_xor_sync(0xffffffffu, mv, o));
        unsigned cand = (bd[0] == mv) ? (unsigned)bi[0] : 0xFFFFFFFFu;
        unsigned widx = __reduce_min_sync(0xffffffffu, cand);
        if (lane == j) keep = (int)widx;
        if ((bd[0] == mv) && ((unsigned)bi[0] == widx)) {
#pragma unroll
            for (int t2 = 0; t2 < KK - 1; t2++) { bd[t2] = bd[t2 + 1]; bi[t2] = bi[t2 + 1]; }
            bd[KK - 1] = 3.4e38f; bi[KK - 1] = 0x7FFFFFFF;
        }
    }
    if (lane < KK) out[(long)gw * KK + lane] = keep;
}

// ---------------------------------------------------------------------------
// GEMM4 (measured-good): 4 output cols/thread via two fma.rn.f32x2.
// ---------------------------------------------------------------------------
template<int RT>
__global__ void gemm4_kernel(const float* __restrict__ A1, int C1,
                             const float* __restrict__ A2, int C2,
                             const float* __restrict__ W,
                             const float* __restrict__ bias,
                             float* __restrict__ out,
                             int rows, int Cout, int relu) {
    extern __shared__ ull shu[];
    const int Cin = C1 + C2;
    int row0 = blockIdx.x * RT;
    for (int i = threadIdx.x; i < RT * Cin; i += blockDim.x) {
        int r = i / Cin, c = i - r * Cin;
        int row = row0 + r;
        float v = 0.f;
        if (row < rows) {
            if (c < C1) v = A1[(long)row * C1 + c];
            else        v = A2[(long)row * C2 + (c - C1)];
        }
        shu[i] = pack2s(v);
    }
    __syncthreads();
    int d0 = (blockIdx.y * blockDim.x + threadIdx.x) * 4;
    if (d0 >= Cout) return;
    ull acc0[RT], acc1[RT];
#pragma unroll
    for (int r = 0; r < RT; r++) { acc0[r] = 0ull; acc1[r] = 0ull; }
    for (int c = 0; c < Cin; c++) {
        ulonglong2 wv = *reinterpret_cast<const ulonglong2*>(W + (long)c * Cout + d0);
        const ull* shc = shu + c;
#pragma unroll
        for (int r = 0; r < RT; r++) {
            ull vv = shc[r * Cin];
            acc0[r] = fma2(vv, wv.x, acc0[r]);
            acc1[r] = fma2(vv, wv.y, acc1[r]);
        }
    }
    float4 bb = bias ? *reinterpret_cast<const float4*>(bias + d0)
                     : make_float4(0.f, 0.f, 0.f, 0.f);
#pragma unroll
    for (int r = 0; r < RT; r++) {
        int row = row0 + r;
        if (row < rows) {
            float2 p0 = unpack2(acc0[r]);
            float2 p1 = unpack2(acc1[r]);
            float v0 = p0.x + bb.x, v1 = p0.y + bb.y;
            float v2 = p1.x + bb.z, v3 = p1.y + bb.w;
            if (relu) {
                v0 = fmaxf(v0, 0.f); v1 = fmaxf(v1, 0.f);
                v2 = fmaxf(v2, 0.f); v3 = fmaxf(v3, 0.f);
            }
            *reinterpret_cast<float4*>(out + (long)row * Cout + d0) =
                make_float4(v0, v1, v2, v3);
        }
    }
}

// 2-col GEMM for Cout=50 (seg head)
__global__ void gemm2_kernel(const float* __restrict__ A1, int C1,
                             const float* __restrict__ W,
                             const float* __restrict__ bias,
                             float* __restrict__ out,
                             int rows, int Cout, int relu) {
    extern __shared__ float sh[];
    const int RT = 16;
    const int Cin = C1;
    int row0 = blockIdx.x * RT;
    for (int i = threadIdx.x; i < RT * Cin; i += blockDim.x) {
        int r = i / Cin, c = i - r * Cin;
        int row = row0 + r;
        sh[i] = (row < rows) ? A1[(long)row * C1 + c] : 0.f;
    }
    __syncthreads();
    int d0 = (blockIdx.y * blockDim.x + threadIdx.x) * 2;
    if (d0 >= Cout) return;
    float2 acc[RT];
#pragma unroll
    for (int r = 0; r < RT; r++) acc[r] = make_float2(0.f, 0.f);
    for (int c = 0; c < Cin; c++) {
        float2 w = *reinterpret_cast<const float2*>(W + (long)c * Cout + d0);
        const float* shc = sh + c;
#pragma unroll
        for (int r = 0; r < RT; r++) {
            float v = shc[r * Cin];
            acc[r].x = fmaf(v, w.x, acc[r].x);
            acc[r].y = fmaf(v, w.y, acc[r].y);
        }
    }
    float2 bb = bias ? *reinterpret_cast<const float2*>(bias + d0)
                     : make_float2(0.f, 0.f);
#pragma unroll
    for (int r = 0; r < RT; r++) {
        int row = row0 + r;
        if (row < rows) {
            float vx = acc[r].x + bb.x, vy = acc[r].y + bb.y;
            if (relu) { vx = fmaxf(vx, 0.f); vy = fmaxf(vy, 0.f); }
            *reinterpret_cast<float2*>(out + (long)row * Cout + d0) = make_float2(vx, vy);
        }
    }
}

// ---------------------------------------------------------------------------
// Fused gather-max: f[b,s,d] = relu( max_k A[b,nidx[b,s,k],d] - Bp[b,s,d] )
// ---------------------------------------------------------------------------
__global__ void gathermax_kernel(const float* __restrict__ A,
                                 const float* __restrict__ Bp,
                                 const int* __restrict__ nidx,
                                 float* __restrict__ f,
                                 int S, int M, int D) {
    __shared__ int idx[KK];
    int bs = blockIdx.x;
    int b = bs / S;
    if (threadIdx.x < KK) idx[threadIdx.x] = nidx[(long)bs * KK + threadIdx.x];
    __syncthreads();
    const float* Abase = A + (long)b * M * D;
    for (int d = threadIdx.x; d < D; d += blockDim.x) {
        float m = -3.4e38f;
#pragma unroll 4
        for (int k = 0; k < KK; k++)
            m = fmaxf(m, Abase[(long)idx[k] * D + d]);
        f[(long)bs * D + d] = fmaxf(m - Bp[(long)bs * D + d], 0.f);
    }
}

// ---------------------------------------------------------------------------
// 3-NN interp, two-phase (selection matches ref knn; weights ref fp_block).
// ---------------------------------------------------------------------------
__global__ void interp3_kernel(const float* __restrict__ xq, int Sq,
                               const float* __restrict__ xr, int Mr,
                               const float* __restrict__ fr, int C,
                               float* __restrict__ out) {
    __shared__ float rx[512], ry[512], rz[512], rr2[512];
    __shared__ float qw[128][3];
    __shared__ int   qb[128][3];
    int nqb = Sq / 128;
    int b  = blockIdx.x / nqb;
    int q0 = (blockIdx.x % nqb) * 128;
    const float* rp = xr + (long)b * Mr * 3;
    for (int j = threadIdx.x; j < Mr; j += blockDim.x) {
        float a = rp[j * 3 + 0], bb = rp[j * 3 + 1], cc = rp[j * 3 + 2];
        rx[j] = a; ry[j] = bb; rz[j] = cc;
        rr2[j] = a * a + bb * bb + cc * cc;
    }
    __syncthreads();
    {
        int qi = q0 + threadIdx.x;
        const float* qp = xq + ((long)b * Sq + qi) * 3;
        float qx = qp[0], qy = qp[1], qz = qp[2];
        float qq = qx * qx + qy * qy + qz * qz;
        float bd0 = 3.4e38f, bd1 = 3.4e38f, bd2 = 3.4e38f;
        int bi0 = 0, bi1 = 0, bi2 = 0;
        for (int m = 0; m < Mr; m++) {
            float d = qq - 2.f * (qx * rx[m] + qy * ry[m] + qz * rz[m]) + rr2[m];
            if (d < bd2) {
                if (d < bd1) {
                    if (d < bd0) { bd2 = bd1; bi2 = bi1; bd1 = bd0; bi1 = bi0; bd0 = d; bi0 = m; }
                    else         { bd2 = bd1; bi2 = bi1; bd1 = d; bi1 = m; }
                } else           { bd2 = d; bi2 = m; }
            }
        }
        int bis[3] = { bi0, bi1, bi2 };
        float w[3]; float ws = 0.f;
#pragma unroll
        for (int j = 0; j < 3; j++) {
            float dx = rx[bis[j]] - qx, dy = ry[bis[j]] - qy, dz = rz[bis[j]] - qz;
            float dd = dx * dx + dy * dy + dz * dz;
            w[j] = 1.f / (dd + 1e-8f);
            ws += w[j];
        }
#pragma unroll
        for (int j = 0; j < 3; j++) {
            qw[threadIdx.x][j] = w[j] / ws;
            qb[threadIdx.x][j] = bis[j];
        }
    }
    __syncthreads();
    for (int qv = 0; qv < 128; ++qv) {
        float w0 = qw[qv][0], w1 = qw[qv][1], w2 = qw[qv][2];
        const float* f0 = fr + ((long)b * Mr + qb[qv][0]) * C;
        const float* f1 = fr + ((long)b * Mr + qb[qv][1]) * C;
        const float* f2 = fr + ((long)b * Mr + qb[qv][2]) * C;
        long ro = ((long)b * Sq + q0 + qv) * C;
        for (int c = threadIdx.x; c < C; c += blockDim.x)
            out[ro + c] = w0 * f0[c] + w1 * f1[c] + w2 * f2[c];
    }
}

// FP0 skip: [cls(16) | xyz(3) | nrm(3)] width-22 rows
__global__ void fp0_skip_kernel(const float* __restrict__ cls,
                                const float* __restrict__ xyz,
                                const float* __restrict__ nrm,
                                float* __restrict__ sk) {
    int total = BB * NN * 22;
    int stride = gridDim.x * blockDim.x;
    for (int i = blockIdx.x * blockDim.x + threadIdx.x; i < total; i += stride) {
        int c = i % 22;
        int row = i / 22;
        int b = row / NN;
        float v;
        if (c < 16)      v = cls[b * 16 + c];
        else if (c < 19) v = xyz[(long)row * 3 + (c - 16)];
        else             v = nrm[(long)row * 3 + (c - 19)];
        sk[i] = v;
    }
}

__global__ void transpose_kernel(const float* __restrict__ in, float* __restrict__ out) {
    __shared__ float tile[32][33];
    int b = blockIdx.z;
    int n0 = blockIdx.x * 32, c0 = blockIdx.y * 32;
    int tx = threadIdx.x, ty = threadIdx.y;
    tile[ty][tx] = in[((long)b * NN + n0 + ty) * 128 + c0 + tx];
    __syncthreads();
    out[((long)b * 128 + c0 + ty) * NN + n0 + tx] = tile[tx][ty];
}

// ============================================================================
// host driver
// ============================================================================
static void launch_g4(const float* A1, int C1, const float* A2, int C2,
                      const float* W, const float* bias, float* out,
                      int rows, int Cout, int relu) {
    int bd = Cout / 4;
    if (bd < 32) bd = 32;
    if (bd > 128) bd = 128;
    int rt = (rows >= 8192) ? 16 : (rows >= 2048) ? 8 : (rows >= 1024) ? 4 : 2;
    dim3 g((rows + rt - 1) / rt, (Cout + bd * 4 - 1) / (bd * 4));
    size_t sm = (size_t)rt * (C1 + C2) * sizeof(ull);
    switch (rt) {
        case 16: gemm4_kernel<16><<<g, bd, sm>>>(A1, C1, A2, C2, W, bias, out, rows, Cout, relu); break;
        case 8:  gemm4_kernel<8><<<g, bd, sm>>>(A1, C1, A2, C2, W, bias, out, rows, Cout, relu); break;
        case 4:  gemm4_kernel<4><<<g, bd, sm>>>(A1, C1, A2, C2, W, bias, out, rows, Cout, relu); break;
        default: gemm4_kernel<2><<<g, bd, sm>>>(A1, C1, A2, C2, W, bias, out, rows, Cout, relu); break;
    }
}

extern "C" void kernel_launch(void* const* d_in, const int* in_sizes, int n_in,
                              void* d_out, int out_size) {
    const float* x    = (const float*)d_in[0];
    const float* cls  = (const float*)d_in[1];
    const float* W0 = (const float*)d_in[2];  const float* b0 = (const float*)d_in[3];
    const float* W1 = (const float*)d_in[4];  const float* b1 = (const float*)d_in[5];
    const float* W2 = (const float*)d_in[6];  const float* b2 = (const float*)d_in[7];
    const float* W3 = (const float*)d_in[8];  const float* b3 = (const float*)d_in[9];
    const float* F3 = (const float*)d_in[10]; const float* fb3 = (const float*)d_in[11];
    const float* F2 = (const float*)d_in[12]; const float* fb2 = (const float*)d_in[13];
    const float* F1 = (const float*)d_in[14]; const float* fb1 = (const float*)d_in[15];
    const float* F0 = (const float*)d_in[16]; const float* fb0 = (const float*)d_in[17];
    const float* Wseg = (const float*)d_in[18]; const float* bseg = (const float*)d_in[19];

    float* arena = 0; int* iar = 0;
    cudaGetSymbolAddress((void**)&arena, g_arena);
    cudaGetSymbolAddress((void**)&iar, g_iarena);

    float* xyz = arena + OFF_XYZ;
    float* nrm = arena + OFF_NRM;
    float* x1 = arena + OFF_X1; float* x2 = arena + OFF_X2;
    float* x3 = arena + OFF_X3; float* x4 = arena + OFF_X4;
    float* f1 = arena + OFF_F1; float* f2 = arena + OFF_F2;
    float* f3 = arena + OFF_F3; float* f4 = arena + OFF_F4;
    float* g3 = arena + OFF_G3; float* g2 = arena + OFF_G2;
    float* g1 = arena + OFF_G1; float* g0 = arena + OFF_G0;
    float* aproj = arena + OFF_APROJ;
    float* bproj = arena + OFF_BPROJ;
    float* ibuf  = arena + OFF_IBUF;
    float* sk0   = arena + OFF_SK0;
    float4* r4   = (float4*)(arena + OFF_R4);
    int* knn = iar;

    cudaFuncSetAttribute((const void*)fps_kernel<512, 8>,
                         cudaFuncAttributeMaxDynamicSharedMemorySize, 3 * NN * 4);

    // side stream + fork/join events (graph-capture compatible fork pattern)
    cudaStream_t sA;
    cudaStreamCreateWithFlags(&sA, cudaStreamNonBlocking);
    cudaEvent_t ev0, ev1, ev2, ev3, ev4;
    cudaEventCreateWithFlags(&ev0, cudaEventDisableTiming);
    cudaEventCreateWithFlags(&ev1, cudaEventDisableTiming);
    cudaEventCreateWithFlags(&ev2, cudaEventDisableTiming);
    cudaEventCreateWithFlags(&ev3, cudaEventDisableTiming);
    cudaEventCreateWithFlags(&ev4, cudaEventDisableTiming);

    // ---- main-stream prologue (independent of FPS) ----
    split_kernel<<<(BB * NN + 255) / 256, 256>>>(x, xyz, nrm);
    prep4_kernel<<<(BB * NN + 255) / 256, 256>>>(xyz, BB * NN, r4);
    fp0_skip_kernel<<<(BB * NN * 22 + 255) / 256, 256>>>(cls, xyz, nrm, sk0);
    launch_g4(xyz, 3, nrm, 3, W0, b0, aproj, BB * NN, 64, 0);     // slot 4: aproj1

    // ---- fork: FPS chain on side stream (reads raw x; only ~8 SMs) ----
    cudaEventRecord(ev0, 0);
    cudaStreamWaitEvent(sA, ev0, 0);
    fps_kernel<512, 8><<<BB, 512, 3 * NN * 4, sA>>>(x, (long)6 * NN, 1, NN, NN, 512, x1);
    cudaEventRecord(ev1, sA);
    fps_kernel<128, 4><<<BB, 128, 3 * 512 * 4, sA>>>(x1, 512 * 3, 3, 1, 512, 256, x2);
    cudaEventRecord(ev2, sA);
    fps_kernel<64, 4><<<BB, 64, 3 * 256 * 4, sA>>>(x2, 256 * 3, 3, 1, 256, 128, x3);
    cudaEventRecord(ev3, sA);
    fps_kernel<32, 4><<<BB, 32, 3 * 128 * 4, sA>>>(x3, 128 * 3, 3, 1, 128, 64, x4);
    cudaEventRecord(ev4, sA);

    // ---- SA1 (needs x1) ----
    cudaStreamWaitEvent(0, ev1, 0);
    knn_warp_kernel<<<BB * 512 / 8, 256>>>(x1, 512, r4, NN, knn);
    launch_g4(x1, 3, 0, 0, W0, 0, bproj, BB * 512, 64, 0);
    gathermax_kernel<<<BB * 512, 64>>>(aproj, bproj, knn, f1, 512, NN, 64);
    prep4_kernel<<<(BB * 512 + 255) / 256, 256>>>(x1, BB * 512, r4);

    // ---- SA2 (needs x2) ----
    cudaStreamWaitEvent(0, ev2, 0);
    knn_warp_kernel<<<BB * 256 / 8, 256>>>(x2, 256, r4, 512, knn);
    launch_g4(x1, 3, f1, 64, W1, b1, aproj, BB * 512, 128, 0);
    launch_g4(x2, 3, 0, 0, W1, 0, bproj, BB * 256, 128, 0);
    gathermax_kernel<<<BB * 256, 128>>>(aproj, bproj, knn, f2, 256, 512, 128);
    prep4_kernel<<<(BB * 256 + 255) / 256, 256>>>(x2, BB * 256, r4);

    // ---- SA3 (needs x3) ----
    cudaStreamWaitEvent(0, ev3, 0);
    knn_warp_kernel<<<BB * 128 / 8, 256>>>(x3, 128, r4, 256, knn);
    launch_g4(x2, 3, f2, 128, W2, b2, aproj, BB * 256, 256, 0);
    launch_g4(x3, 3, 0, 0, W2, 0, bproj, BB * 128, 256, 0);
    gathermax_kernel<<<BB * 128, 128>>>(aproj, bproj, knn, f3, 128, 256, 256);
    prep4_kernel<<<(BB * 128 + 255) / 256, 256>>>(x3, BB * 128, r4);

    // ---- SA4 (needs x4) — also joins side stream ----
    cudaStreamWaitEvent(0, ev4, 0);
    knn_warp_kernel<<<BB * 64 / 8, 256>>>(x4, 64, r4, 128, knn);
    launch_g4(x3, 3, f3, 256, W3, b3, aproj, BB * 128, 512, 0);
    launch_g4(x4, 3, 0, 0, W3, 0, bproj, BB * 64, 512, 0);
    gathermax_kernel<<<BB * 64, 128>>>(aproj, bproj, knn, f4, 64, 128, 512);

    // ---- FP3 ----
    interp3_kernel<<<BB, 128>>>(x3, 128, x4, 64, f4, 512, ibuf);
    launch_g4(ibuf, 512, f3, 256, F3, fb3, g3, BB * 128, 512, 1);

    // ---- FP2 ----
    interp3_kernel<<<BB * 2, 128>>>(x2, 256, x3, 128, g3, 512, ibuf);
    launch_g4(ibuf, 512, f2, 128, F2, fb2, g2, BB * 256, 256, 1);

    // ---- FP1 ----
    interp3_kernel<<<BB * 4, 128>>>(x1, 512, x2, 256, g2, 256, ibuf);
    launch_g4(ibuf, 256, f1, 64, F1, fb1, g1, BB * 512, 128, 1);

    // ---- FP0 ----
    interp3_kernel<<<BB * 32, 128>>>(xyz, NN, x1, 512, g1, 128, ibuf);
    launch_g4(ibuf, 128, sk0, 22, F0, fb0, g0, BB * NN, 128, 1);

    // ---- seg head ----
    {
        dim3 g((BB * NN + 15) / 16, 1);
        gemm2_kernel<<<g, 32, 16 * 128 * sizeof(float)>>>(
            g0, 128, Wseg, bseg, (float*)d_out, BB * NN, 50, 0);
    }

    // ---- g0 transposed ----
    const int RESULT_SZ = BB * NN * 50;
    const int G0T_SZ = BB * 128 * NN;
    if (out_size >= RESULT_SZ + G0T_SZ) {
        dim3 g(NN / 32, 128 / 32, BB);
        transpose_kernel<<<g, dim3(32, 32)>>>(g0, (float*)d_out + RESULT_SZ);
    }

    // cleanup: only when NOT capturing (destroying capture-referenced objects
    // is illegal; the few leaked handles during capture are host-side only)
    cudaStreamCaptureStatus cst = cudaStreamCaptureStatusNone;
    cudaStreamIsCapturing(0, &cst);
    if (cst == cudaStreamCaptureStatusNone) {
        cudaEventDestroy(ev0); cudaEventDestroy(ev1); cudaEventDestroy(ev2);
        cudaEventDestroy(ev3); cudaEventDestroy(ev4);
        cudaStreamDestroy(sA);
    }
}